// round 16
// baseline (speedup 1.0000x reference)
#include <cuda_runtime.h>
#include <cuda_fp16.h>
#include <cstdint>

#define NN   50000
#define BB   2
#define FIN  128
#define FOUT 64
#define OC   128          // B*FOUT = gather row width
#define EE   800000
#define ROWS (BB * NN)    // 100000

#define TILE_M 128
#define NT     128        // combined cols: 0..63 -> W -> g_xt, 64..127 -> Wself -> out
#define KHALF  64
#define STRIDE 72         // frag-row stride in floats; conflict-free LDS.64

// smem float offsets: B frags (hi/lo) + A raw-f32 region (doubles as WPL staging)
#define B_HI 0
#define B_LO (B_HI + NT * STRIDE)          //  9216
#define AF   (B_LO + NT * STRIDE)          // 18432  A f32 region (128*72); WPL overlaps here
#define SM_FLOATS (AF + TILE_M * STRIDE)   // 27648
#define SM_BYTES  (SM_FLOATS * 4)          // 110592  -> 2 CTAs/SM

// Scratch (allocation-free rule: __device__ global). fp16: halves gather traffic.
__device__ __half g_xt[NN * OC];  // x@W as (n, b*FOUT + o), fp16

__device__ __forceinline__ uint32_t f2tf32(float f) {
    uint32_t u;
    asm("cvt.rna.tf32.f32 %0, %1;" : "=r"(u) : "f"(f));
    return u;
}
__device__ __forceinline__ void mma_tf32(float* d, uint32_t a0, uint32_t a1, uint32_t a2,
                                         uint32_t a3, uint32_t b0, uint32_t b1) {
    asm volatile(
        "mma.sync.aligned.m16n8k8.row.col.f32.tf32.tf32.f32 "
        "{%0,%1,%2,%3}, {%4,%5,%6,%7}, {%8,%9}, {%0,%1,%2,%3};"
        : "+f"(d[0]), "+f"(d[1]), "+f"(d[2]), "+f"(d[3])
        : "r"(a0), "r"(a1), "r"(a2), "r"(a3), "r"(b0), "r"(b1));
}
// k-permutation within each 8-group: value q -> pos (q<4 ? 2q : 2(q-4)+1):
// values (q, q+4) are adjacent -> all fragment pair reads are LDS.64.

// ---------------------------------------------------------------------------
// 3xTF32 tensor GEMM (R15, measured 81.8us): A raw-f32 staged, hi/lo split in
// registers in the mainloop; 2 CTAs/SM. Only the g_xt store dtype changed.
// ---------------------------------------------------------------------------
__global__ __launch_bounds__(256, 2) void gemm_kernel(
    const float* __restrict__ x, const float* __restrict__ W,
    const float* __restrict__ Wself, const float* __restrict__ bself,
    float* __restrict__ out)
{
    extern __shared__ float sm[];
    const int t = threadIdx.x;
    const int w = t >> 5, lane = t & 31;
    const int g = lane >> 2, tg = lane & 3;
    const int p  = w & 3;          // m-pair (rows 32p..32p+31)
    const int nh = w >> 2;         // n-half (cols 64*nh..)
    const long rb = (long)blockIdx.x * TILE_M;

    float acc[2][8][4];
    #pragma unroll
    for (int ms = 0; ms < 2; ms++)
        #pragma unroll
        for (int nt = 0; nt < 8; nt++)
            #pragma unroll
            for (int e = 0; e < 4; e++) acc[ms][nt][e] = 0.f;

    #pragma unroll 1
    for (int h = 0; h < 2; h++) {
        // ---- stage plain weights for this k-half into AF region (WPL overlap)
        #pragma unroll
        for (int i = 0; i < 8; i++) {
            int v = i * 256 + t;                     // 2048 float4 chunks
            int mat = v >> 10, rem = v & 1023;
            int fl = rem >> 4, o4 = (rem & 15) * 4;
            const float* src = (mat ? Wself : W) + (long)(h * KHALF + fl) * FOUT + o4;
            float4 u = *(const float4*)src;
            *(float4*)(sm + AF + fl * NT + mat * 64 + o4) = u;
        }
        __syncthreads();
        // ---- build B fragments (hi/lo) from WPL transpose ----
        #pragma unroll
        for (int i = 0; i < 4; i++) {
            int v = i * 256 + t;
            int n = v & 127, s = v >> 7;             // s = k-step
            float wv[8];
            #pragma unroll
            for (int q = 0; q < 8; q++)
                wv[q] = sm[AF + (s * 8 + q) * NT + n];
            uint32_t hi[8], lo[8];
            #pragma unroll
            for (int q = 0; q < 8; q++) {
                hi[q] = f2tf32(wv[q]);
                lo[q] = f2tf32(wv[q] - __uint_as_float(hi[q]));
            }
            uint32_t* bh = (uint32_t*)(sm + B_HI + n * STRIDE + s * 8);
            uint32_t* bl = (uint32_t*)(sm + B_LO + n * STRIDE + s * 8);
            *(uint4*)bh       = make_uint4(hi[0], hi[4], hi[1], hi[5]);
            *(uint4*)(bh + 4) = make_uint4(hi[2], hi[6], hi[3], hi[7]);
            *(uint4*)bl       = make_uint4(lo[0], lo[4], lo[1], lo[5]);
            *(uint4*)(bl + 4) = make_uint4(lo[2], lo[6], lo[3], lo[7]);
        }
        __syncthreads();                             // WPL reads done
        // ---- stage A as raw f32, permuted, into AF (overwrites WPL) ----
        #pragma unroll
        for (int i = 0; i < 4; i++) {
            int v = i * 256 + t;
            int row = v & 127, c = v >> 7;           // c = k-step 0..7
            long gr = rb + row;
            float4 u0, u1;
            if (gr < ROWS) {
                u0 = *(const float4*)(x + gr * FIN + h * KHALF + c * 8);
                u1 = *(const float4*)(x + gr * FIN + h * KHALF + c * 8 + 4);
            } else {
                u0 = make_float4(0.f, 0.f, 0.f, 0.f);
                u1 = u0;
            }
            float* a = sm + AF + row * STRIDE + c * 8;
            *(float4*)a       = make_float4(u0.x, u1.x, u0.y, u1.y);
            *(float4*)(a + 4) = make_float4(u0.z, u1.z, u0.w, u1.w);
        }
        __syncthreads();

        // ---- main loop: 8 k-steps; A hi/lo split in registers ----
        #pragma unroll
        for (int s = 0; s < 8; s++) {
            uint2 af[2][2];
            #pragma unroll
            for (int ms = 0; ms < 2; ms++) {
                int r0 = p * 32 + ms * 16 + g;
                af[ms][0] = *(const uint2*)(sm + AF + r0 * STRIDE + s * 8 + 2 * tg);
                af[ms][1] = *(const uint2*)(sm + AF + (r0 + 8) * STRIDE + s * 8 + 2 * tg);
            }
            uint32_t ahx[2][2], ahy[2][2], alx[2][2], aly[2][2];
            #pragma unroll
            for (int ms = 0; ms < 2; ms++)
                #pragma unroll
                for (int hf = 0; hf < 2; hf++) {
                    float f0 = __uint_as_float(af[ms][hf].x);
                    float f1 = __uint_as_float(af[ms][hf].y);
                    ahx[ms][hf] = f2tf32(f0);
                    alx[ms][hf] = f2tf32(f0 - __uint_as_float(ahx[ms][hf]));
                    ahy[ms][hf] = f2tf32(f1);
                    aly[ms][hf] = f2tf32(f1 - __uint_as_float(ahy[ms][hf]));
                }
            uint2 bh[8], bl[8];
            #pragma unroll
            for (int nt = 0; nt < 8; nt++) {
                int nr = nh * 64 + nt * 8 + g;
                bh[nt] = *(const uint2*)(sm + B_HI + nr * STRIDE + s * 8 + 2 * tg);
                bl[nt] = *(const uint2*)(sm + B_LO + nr * STRIDE + s * 8 + 2 * tg);
            }
            #pragma unroll
            for (int ms = 0; ms < 2; ms++) {
                #pragma unroll
                for (int nt = 0; nt < 8; nt++) {
                    float* d = acc[ms][nt];
                    mma_tf32(d, ahx[ms][0], ahx[ms][1], ahy[ms][0], ahy[ms][1],
                             bh[nt].x, bh[nt].y);                       // hi*hi
                    mma_tf32(d, ahx[ms][0], ahx[ms][1], ahy[ms][0], ahy[ms][1],
                             bl[nt].x, bl[nt].y);                       // hi*lo
                    mma_tf32(d, alx[ms][0], alx[ms][1], aly[ms][0], aly[ms][1],
                             bh[nt].x, bh[nt].y);                       // lo*hi
                }
            }
        }
        __syncthreads();                             // AF about to be restaged
    }

    // ---- epilogue: g_xt as fp16 (half2 stores), out as f32 ----
    #pragma unroll
    for (int ms = 0; ms < 2; ms++) {
        #pragma unroll
        for (int nt = 0; nt < 8; nt++) {
            int col = nh * 64 + nt * 8 + 2 * tg;
            long r0 = rb + p * 32 + ms * 16 + g;
            long r1 = r0 + 8;
            float2 v0 = make_float2(acc[ms][nt][0], acc[ms][nt][1]);
            float2 v1 = make_float2(acc[ms][nt][2], acc[ms][nt][3]);
            if (nh == 0) {          // neighbor path -> g_xt[(n)*128 + b*64 + col]
                if (r0 < ROWS) {
                    int b = (int)(r0 / NN), n = (int)(r0 % NN);
                    *(__half2*)(g_xt + (long)n * OC + b * FOUT + col) =
                        __floats2half2_rn(v0.x, v0.y);
                }
                if (r1 < ROWS) {
                    int b = (int)(r1 / NN), n = (int)(r1 % NN);
                    *(__half2*)(g_xt + (long)n * OC + b * FOUT + col) =
                        __floats2half2_rn(v1.x, v1.y);
                }
            } else {                // self path -> out + bias
                int oc = col - 64;
                float2 bv = *(const float2*)(bself + oc);
                v0.x += bv.x; v0.y += bv.y;
                v1.x += bv.x; v1.y += bv.y;
                if (r0 < ROWS) *(float2*)(out + r0 * FOUT + oc) = v0;
                if (r1 < ROWS) *(float2*)(out + r1 * FOUT + oc) = v1;
            }
        }
    }
}

// ---------------------------------------------------------------------------
// Edge scatter: one warp per edge, fp16 gather (256B/edge instead of 512B),
// f32 vector RED directly into out. Lane l<16 -> b=0; l>=16 -> b=1.
// ---------------------------------------------------------------------------
__global__ __launch_bounds__(256) void scatter_kernel(
    const int* __restrict__ erow, const int* __restrict__ ecol,
    const float* __restrict__ eval, float* __restrict__ out)
{
    int e = blockIdx.x * 8 + (threadIdx.x >> 5);   // 800000 / 8 = 100000 blocks, exact
    int lane = threadIdx.x & 31;
    int r = erow[e], c = ecol[e];
    float v = eval[e];
    uint2 raw = *(const uint2*)(g_xt + (long)c * OC + lane * 4);   // 4 halves, 8B
    __half2 h0 = *(__half2*)&raw.x;
    __half2 h1 = *(__half2*)&raw.y;
    float2 f0 = __half22float2(h0);
    float2 f1 = __half22float2(h1);
    int b = lane >> 4;
    float* dst = out + ((long)b * NN + r) * FOUT + (lane & 15) * 4;
    asm volatile("red.global.add.v4.f32 [%0], {%1, %2, %3, %4};"
                 :: "l"(dst), "f"(f0.x * v), "f"(f0.y * v), "f"(f1.x * v), "f"(f1.y * v)
                 : "memory");
}

// ---------------------------------------------------------------------------
// Final epilogue: in-place relu over out.
// ---------------------------------------------------------------------------
__global__ __launch_bounds__(256) void relu_kernel(float* __restrict__ out)
{
    long i = (long)blockIdx.x * 256 + threadIdx.x;   // 1.6M float4 units, exact grid
    float4 s = *(float4*)(out + i * 4);
    s.x = fmaxf(s.x, 0.f);
    s.y = fmaxf(s.y, 0.f);
    s.z = fmaxf(s.z, 0.f);
    s.w = fmaxf(s.w, 0.f);
    *(float4*)(out + i * 4) = s;
}

extern "C" void kernel_launch(void* const* d_in, const int* in_sizes, int n_in,
                              void* d_out, int out_size)
{
    const float* x     = (const float*)d_in[0];
    const float* W     = (const float*)d_in[1];
    const float* Wself = (const float*)d_in[2];
    const float* bself = (const float*)d_in[3];
    const int*   erow  = (const int*)d_in[4];
    const int*   ecol  = (const int*)d_in[5];
    const float* eval  = (const float*)d_in[6];
    float* out = (float*)d_out;

    cudaFuncSetAttribute(gemm_kernel, cudaFuncAttributeMaxDynamicSharedMemorySize, SM_BYTES);
    int gblocks = (ROWS + TILE_M - 1) / TILE_M;                        // 782
    gemm_kernel<<<gblocks, 256, SM_BYTES>>>(x, W, Wself, bself, out);

    scatter_kernel<<<EE / 8, 256>>>(erow, ecol, eval, out);            // 100000 blocks

    relu_kernel<<<(long)BB * NN * FOUT / 4 / 256, 256>>>(out);         // 6250 blocks
}

// round 17
// speedup vs baseline: 1.1414x; 1.1414x over previous
#include <cuda_runtime.h>
#include <cstdint>

#define NN   50000
#define BB   2
#define FIN  128
#define FOUT 64
#define OC   128          // B*FOUT = gather row width
#define EE   800000
#define ROWS (BB * NN)    // 100000

#define TILE_M 128
#define NT     128        // combined cols: 0..63 -> W -> g_xt, 64..127 -> Wself -> out
#define KHALF  64
#define STRIDE 72         // frag-row stride in floats; conflict-free LDS.64

// smem float offsets: B frags (hi only, 2xTF32) + A raw-f32 region (doubles as WPL)
#define B_HI 0
#define AF   (B_HI + NT * STRIDE)          //  9216  A f32 region (128*72); WPL overlaps here
#define SM_FLOATS (AF + TILE_M * STRIDE)   // 18432
#define SM_BYTES  (SM_FLOATS * 4)          // 73728  -> 2 CTAs/SM (reg-limited), L1 headroom up

// Scratch (allocation-free rule: __device__ global) — back to f32 (fp16 was neutral)
__device__ float g_xt[NN * OC];   // x@W laid out as (n, b*FOUT + o)  -- gather source

__device__ __forceinline__ uint32_t f2tf32(float f) {
    uint32_t u;
    asm("cvt.rna.tf32.f32 %0, %1;" : "=r"(u) : "f"(f));
    return u;
}
__device__ __forceinline__ void mma_tf32(float* d, uint32_t a0, uint32_t a1, uint32_t a2,
                                         uint32_t a3, uint32_t b0, uint32_t b1) {
    asm volatile(
        "mma.sync.aligned.m16n8k8.row.col.f32.tf32.tf32.f32 "
        "{%0,%1,%2,%3}, {%4,%5,%6,%7}, {%8,%9}, {%0,%1,%2,%3};"
        : "+f"(d[0]), "+f"(d[1]), "+f"(d[2]), "+f"(d[3])
        : "r"(a0), "r"(a1), "r"(a2), "r"(a3), "r"(b0), "r"(b1));
}
// k-permutation within each 8-group: value q -> pos (q<4 ? 2q : 2(q-4)+1):
// values (q, q+4) are adjacent -> all fragment pair reads are LDS.64.

// ---------------------------------------------------------------------------
// 2xTF32 tensor GEMM: A split hi/lo in registers (exact to ~2^-22), B single
// tf32 (error ~2.8e-4). Two MMAs per k-step per n-tile instead of three.
// ---------------------------------------------------------------------------
__global__ __launch_bounds__(256, 2) void gemm_kernel(
    const float* __restrict__ x, const float* __restrict__ W,
    const float* __restrict__ Wself, const float* __restrict__ bself,
    float* __restrict__ out)
{
    extern __shared__ float sm[];
    const int t = threadIdx.x;
    const int w = t >> 5, lane = t & 31;
    const int g = lane >> 2, tg = lane & 3;
    const int p  = w & 3;          // m-pair (rows 32p..32p+31)
    const int nh = w >> 2;         // n-half (cols 64*nh..)
    const long rb = (long)blockIdx.x * TILE_M;

    float acc[2][8][4];
    #pragma unroll
    for (int ms = 0; ms < 2; ms++)
        #pragma unroll
        for (int nt = 0; nt < 8; nt++)
            #pragma unroll
            for (int e = 0; e < 4; e++) acc[ms][nt][e] = 0.f;

    #pragma unroll 1
    for (int h = 0; h < 2; h++) {
        // ---- stage plain weights for this k-half into AF region (WPL overlap)
        #pragma unroll
        for (int i = 0; i < 8; i++) {
            int v = i * 256 + t;                     // 2048 float4 chunks
            int mat = v >> 10, rem = v & 1023;
            int fl = rem >> 4, o4 = (rem & 15) * 4;
            const float* src = (mat ? Wself : W) + (long)(h * KHALF + fl) * FOUT + o4;
            float4 u = *(const float4*)src;
            *(float4*)(sm + AF + fl * NT + mat * 64 + o4) = u;
        }
        __syncthreads();
        // ---- build B fragments (hi only) from WPL transpose ----
        #pragma unroll
        for (int i = 0; i < 4; i++) {
            int v = i * 256 + t;
            int n = v & 127, s = v >> 7;             // s = k-step
            uint32_t hi[8];
            #pragma unroll
            for (int q = 0; q < 8; q++)
                hi[q] = f2tf32(sm[AF + (s * 8 + q) * NT + n]);
            uint32_t* bh = (uint32_t*)(sm + B_HI + n * STRIDE + s * 8);
            *(uint4*)bh       = make_uint4(hi[0], hi[4], hi[1], hi[5]);
            *(uint4*)(bh + 4) = make_uint4(hi[2], hi[6], hi[3], hi[7]);
        }
        __syncthreads();                             // WPL reads done
        // ---- stage A as raw f32, permuted, into AF (overwrites WPL) ----
        #pragma unroll
        for (int i = 0; i < 4; i++) {
            int v = i * 256 + t;
            int row = v & 127, c = v >> 7;           // c = k-step 0..7
            long gr = rb + row;
            float4 u0, u1;
            if (gr < ROWS) {
                u0 = *(const float4*)(x + gr * FIN + h * KHALF + c * 8);
                u1 = *(const float4*)(x + gr * FIN + h * KHALF + c * 8 + 4);
            } else {
                u0 = make_float4(0.f, 0.f, 0.f, 0.f);
                u1 = u0;
            }
            float* a = sm + AF + row * STRIDE + c * 8;
            *(float4*)a       = make_float4(u0.x, u1.x, u0.y, u1.y);
            *(float4*)(a + 4) = make_float4(u0.z, u1.z, u0.w, u1.w);
        }
        __syncthreads();

        // ---- main loop: 8 k-steps; A hi/lo split in registers, B hi only ----
        #pragma unroll
        for (int s = 0; s < 8; s++) {
            uint2 af[2][2];
            #pragma unroll
            for (int ms = 0; ms < 2; ms++) {
                int r0 = p * 32 + ms * 16 + g;
                af[ms][0] = *(const uint2*)(sm + AF + r0 * STRIDE + s * 8 + 2 * tg);
                af[ms][1] = *(const uint2*)(sm + AF + (r0 + 8) * STRIDE + s * 8 + 2 * tg);
            }
            uint32_t ahx[2][2], ahy[2][2], alx[2][2], aly[2][2];
            #pragma unroll
            for (int ms = 0; ms < 2; ms++)
                #pragma unroll
                for (int hf = 0; hf < 2; hf++) {
                    float f0 = __uint_as_float(af[ms][hf].x);
                    float f1 = __uint_as_float(af[ms][hf].y);
                    ahx[ms][hf] = f2tf32(f0);
                    alx[ms][hf] = f2tf32(f0 - __uint_as_float(ahx[ms][hf]));
                    ahy[ms][hf] = f2tf32(f1);
                    aly[ms][hf] = f2tf32(f1 - __uint_as_float(ahy[ms][hf]));
                }
            uint2 bh[8];
            #pragma unroll
            for (int nt = 0; nt < 8; nt++) {
                int nr = nh * 64 + nt * 8 + g;
                bh[nt] = *(const uint2*)(sm + B_HI + nr * STRIDE + s * 8 + 2 * tg);
            }
            #pragma unroll
            for (int ms = 0; ms < 2; ms++) {
                #pragma unroll
                for (int nt = 0; nt < 8; nt++) {
                    float* d = acc[ms][nt];
                    mma_tf32(d, ahx[ms][0], ahx[ms][1], ahy[ms][0], ahy[ms][1],
                             bh[nt].x, bh[nt].y);                       // hi_A * B
                    mma_tf32(d, alx[ms][0], alx[ms][1], aly[ms][0], aly[ms][1],
                             bh[nt].x, bh[nt].y);                       // lo_A * B
                }
            }
        }
        __syncthreads();                             // AF about to be restaged
    }

    // ---- epilogue: direct float2 stores ----
    #pragma unroll
    for (int ms = 0; ms < 2; ms++) {
        #pragma unroll
        for (int nt = 0; nt < 8; nt++) {
            int col = nh * 64 + nt * 8 + 2 * tg;
            long r0 = rb + p * 32 + ms * 16 + g;
            long r1 = r0 + 8;
            float2 v0 = make_float2(acc[ms][nt][0], acc[ms][nt][1]);
            float2 v1 = make_float2(acc[ms][nt][2], acc[ms][nt][3]);
            if (nh == 0) {          // neighbor path -> g_xt[(n)*128 + b*64 + col]
                if (r0 < ROWS) {
                    int b = (int)(r0 / NN), n = (int)(r0 % NN);
                    *(float2*)(g_xt + (long)n * OC + b * FOUT + col) = v0;
                }
                if (r1 < ROWS) {
                    int b = (int)(r1 / NN), n = (int)(r1 % NN);
                    *(float2*)(g_xt + (long)n * OC + b * FOUT + col) = v1;
                }
            } else {                // self path -> out + bias
                int oc = col - 64;
                float2 bv = *(const float2*)(bself + oc);
                v0.x += bv.x; v0.y += bv.y;
                v1.x += bv.x; v1.y += bv.y;
                if (r0 < ROWS) *(float2*)(out + r0 * FOUT + oc) = v0;
                if (r1 < ROWS) *(float2*)(out + r1 * FOUT + oc) = v1;
            }
        }
    }
}

// ---------------------------------------------------------------------------
// Edge scatter: one warp per edge, f32 gather, vector RED directly into out
// (self+bias already there). At the LTS RED-op throughput floor (measured).
// ---------------------------------------------------------------------------
__global__ __launch_bounds__(256) void scatter_kernel(
    const int* __restrict__ erow, const int* __restrict__ ecol,
    const float* __restrict__ eval, float* __restrict__ out)
{
    int e = blockIdx.x * 8 + (threadIdx.x >> 5);   // 800000 / 8 = 100000 blocks, exact
    int lane = threadIdx.x & 31;
    int r = erow[e], c = ecol[e];
    float v = eval[e];
    float4 s = *(const float4*)(g_xt + (long)c * OC + lane * 4);
    int b = lane >> 4;
    float* dst = out + ((long)b * NN + r) * FOUT + (lane & 15) * 4;
    asm volatile("red.global.add.v4.f32 [%0], {%1, %2, %3, %4};"
                 :: "l"(dst), "f"(s.x * v), "f"(s.y * v), "f"(s.z * v), "f"(s.w * v)
                 : "memory");
}

// ---------------------------------------------------------------------------
// Final epilogue: in-place relu over out.
// ---------------------------------------------------------------------------
__global__ __launch_bounds__(256) void relu_kernel(float* __restrict__ out)
{
    long i = (long)blockIdx.x * 256 + threadIdx.x;   // 1.6M float4 units, exact grid
    float4 s = *(float4*)(out + i * 4);
    s.x = fmaxf(s.x, 0.f);
    s.y = fmaxf(s.y, 0.f);
    s.z = fmaxf(s.z, 0.f);
    s.w = fmaxf(s.w, 0.f);
    *(float4*)(out + i * 4) = s;
}

extern "C" void kernel_launch(void* const* d_in, const int* in_sizes, int n_in,
                              void* d_out, int out_size)
{
    const float* x     = (const float*)d_in[0];
    const float* W     = (const float*)d_in[1];
    const float* Wself = (const float*)d_in[2];
    const float* bself = (const float*)d_in[3];
    const int*   erow  = (const int*)d_in[4];
    const int*   ecol  = (const int*)d_in[5];
    const float* eval  = (const float*)d_in[6];
    float* out = (float*)d_out;

    cudaFuncSetAttribute(gemm_kernel, cudaFuncAttributeMaxDynamicSharedMemorySize, SM_BYTES);
    int gblocks = (ROWS + TILE_M - 1) / TILE_M;                        // 782
    gemm_kernel<<<gblocks, 256, SM_BYTES>>>(x, W, Wself, bself, out);

    scatter_kernel<<<EE / 8, 256>>>(erow, ecol, eval, out);            // 100000 blocks

    relu_kernel<<<(long)BB * NN * FOUT / 4 / 256, 256>>>(out);         // 6250 blocks
}